// round 8
// baseline (speedup 1.0000x reference)
#include <cuda_runtime.h>

#define SEQ   512
#define BATCH 2048
#define IND   4
#define H     50
#define BT    16                 // batch tile per CTA
#define NCTA  (BATCH / BT)       // 128
#define NTHR  384                // 12 warps; big reg budget (170/thread)
#define HP    56                 // floats per h row: 50 h + 4 x + 2 pad = 28 pairs
#define NPAIR 28
#define GS    17                 // gate-row stride in ull (conflict-free, coprime 16)

typedef unsigned long long ull;

// ---- packed dual-fp32 (sm_103a FFMA2 path, PTX-only) ----
__device__ __forceinline__ ull pack2(float lo, float hi) {
    ull r; asm("mov.b64 %0, {%1, %2};" : "=l"(r) : "f"(lo), "f"(hi)); return r;
}
__device__ __forceinline__ void unpack2(ull v, float& lo, float& hi) {
    asm("mov.b64 {%0, %1}, %2;" : "=f"(lo), "=f"(hi) : "l"(v));
}
__device__ __forceinline__ void fma2(ull& d, ull a, ull b) {
    asm("fma.rn.f32x2 %0, %1, %2, %0;" : "+l"(d) : "l"(a), "l"(b));
}
__device__ __forceinline__ ull add2(ull a, ull b) {
    ull r; asm("add.rn.f32x2 %0, %1, %2;" : "=l"(r) : "l"(a), "l"(b)); return r;
}

// ---- fast activations (known-good: final rel_err ~1.5e-7) ----
__device__ __forceinline__ float sigf(float x) {
    return __fdividef(1.0f, 1.0f + __expf(-x));
}
__device__ __forceinline__ float tanh_fast(float x) {
    float ax = fabsf(x);
    float e  = __expf(-2.0f * ax);
    float t  = __fdividef(1.0f - e, 1.0f + e);
    return copysignf(t, x);
}

struct Smem {
    float h1s [BT][HP];      // layer1 h (+ x in slots 50..53, zeros 54..55)
    float h1rs[BT][HP];      // relu(h1)  (slots 50..55 stay zero)
    float h2s [BT][HP];      // layer2 h
    float h2rs[BT][HP];      // relu(h2)
    ull   g1p [200 * GS];    // L1 gate pair-sums   (stride 17: conflict-free)
    ull   g2ap[200 * GS];    // L2 w_ih2 part
    ull   g2bp[200 * GS];    // L2 w_hh2 part
    float b1c[200];          // b_ih1 + b_hh1
    float b2c[200];          // b_ih2 + b_hh2
    float xs[BT][IND];       // staged x(t+1)
    float wfcs[52];
    float bfcs;
};

__device__ __forceinline__ float hsum2(ull v, float bias) {
    float lo, hi; unpack2(v, lo, hi);
    return (lo + hi) + bias;
}

__device__ __forceinline__ void l1_update(Smem* S, int u, int b, float& c) {
    float gi = hsum2(S->g1p[(      u) * GS + b], S->b1c[u]);
    float gf = hsum2(S->g1p[(H   + u) * GS + b], S->b1c[H + u]);
    float gg = hsum2(S->g1p[(2*H + u) * GS + b], S->b1c[2*H + u]);
    float go = hsum2(S->g1p[(3*H + u) * GS + b], S->b1c[3*H + u]);
    float cn = sigf(gf) * c + sigf(gi) * tanh_fast(gg);
    c = cn;
    float hv = sigf(go) * tanh_fast(cn);
    S->h1s[b][u]  = hv;
    S->h1rs[b][u] = fmaxf(hv, 0.f);
}

__device__ __forceinline__ void l2_update(Smem* S, int u, int b, float& c) {
    float gi = hsum2(add2(S->g2ap[(      u) * GS + b], S->g2bp[(      u) * GS + b]), S->b2c[u]);
    float gf = hsum2(add2(S->g2ap[(H   + u) * GS + b], S->g2bp[(H   + u) * GS + b]), S->b2c[H + u]);
    float gg = hsum2(add2(S->g2ap[(2*H + u) * GS + b], S->g2bp[(2*H + u) * GS + b]), S->b2c[2*H + u]);
    float go = hsum2(add2(S->g2ap[(3*H + u) * GS + b], S->g2bp[(3*H + u) * GS + b]), S->b2c[3*H + u]);
    float cn = sigf(gf) * c + sigf(gi) * tanh_fast(gg);
    c = cn;
    float hv = sigf(go) * tanh_fast(cn);
    S->h2s[b][u]  = hv;
    S->h2rs[b][u] = fmaxf(hv, 0.f);
}

__global__ __launch_bounds__(NTHR, 1)
void lstm_fused_kernel(
    const float* __restrict__ x,
    const float* __restrict__ w_ih1, const float* __restrict__ w_hh1,
    const float* __restrict__ b_ih1, const float* __restrict__ b_hh1,
    const float* __restrict__ w_ih2, const float* __restrict__ w_hh2,
    const float* __restrict__ b_ih2, const float* __restrict__ b_hh2,
    const float* __restrict__ w_fc,  const float* __restrict__ b_fc,
    float* __restrict__ out)
{
    extern __shared__ char smem_raw[];
    Smem* S = (Smem*)smem_raw;

    const int tid = threadIdx.x;
    const int B0  = blockIdx.x * BT;

    // ---- init ----
    for (int i = tid; i < 4 * BT * HP; i += NTHR)
        ((float*)S->h1s)[i] = 0.f;                 // zeros 4 h arrays incl pads
    for (int i = tid; i < 200; i += NTHR) {
        S->b1c[i] = b_ih1[i] + b_hh1[i];
        S->b2c[i] = b_ih2[i] + b_hh2[i];
    }
    if (tid < 52)  S->wfcs[tid] = (tid < H) ? w_fc[tid] : 0.f;
    if (tid == 0)  S->bfcs = b_fc[0];
    __syncthreads();
    if (tid < BT * IND) {                          // x(0) into h1 row slots
        int b = tid >> 2, d = tid & 3;
        S->h1s[b][H + d] = x[(B0 + b) * IND + d];
    }

    // ---- per-thread packed weights: TWO rows per thread (g and g+100) ----
    // band 0 [0,100)   : w_hh1/w_ih1 rows g,g+100 ; reads h1s  ; -> g1p
    // band 1 [100,200) : w_ih2 rows g,g+100       ; reads h1rs ; -> g2ap
    // band 2 [200,300) : w_hh2 rows g,g+100       ; reads h2s  ; -> g2bp
    ull w2lo[NPAIR], w2hi[NPAIR];
#pragma unroll
    for (int q = 0; q < NPAIR; q++) { w2lo[q] = 0ULL; w2hi[q] = 0ULL; }
    const ull* hb  = (const ull*)S->h1s;
    ull*       gd0 = S->g1p;
    ull*       gd1 = S->g1p;

    if (tid < 300) {
        const int band = tid / 100;
        const int g    = tid - band * 100;         // rows g and g+100 of band
        const float* wsrc = (band == 0) ? w_hh1 : (band == 1) ? w_ih2 : w_hh2;
#pragma unroll
        for (int q = 0; q < 25; q++) {
            w2lo[q] = pack2(wsrc[(g      ) * H + 2 * q], wsrc[(g      ) * H + 2 * q + 1]);
            w2hi[q] = pack2(wsrc[(g + 100) * H + 2 * q], wsrc[(g + 100) * H + 2 * q + 1]);
        }
        if (band == 0) {
            w2lo[25] = pack2(w_ih1[(g      ) * IND + 0], w_ih1[(g      ) * IND + 1]);
            w2lo[26] = pack2(w_ih1[(g      ) * IND + 2], w_ih1[(g      ) * IND + 3]);
            w2hi[25] = pack2(w_ih1[(g + 100) * IND + 0], w_ih1[(g + 100) * IND + 1]);
            w2hi[26] = pack2(w_ih1[(g + 100) * IND + 2], w_ih1[(g + 100) * IND + 3]);
            hb = (const ull*)S->h1s;  gd0 = S->g1p  + g * GS; gd1 = S->g1p  + (g + 100) * GS;
        } else if (band == 1) {
            hb = (const ull*)S->h1rs; gd0 = S->g2ap + g * GS; gd1 = S->g2ap + (g + 100) * GS;
        } else {
            hb = (const ull*)S->h2s;  gd0 = S->g2bp + g * GS; gd1 = S->g2bp + (g + 100) * GS;
        }
    }

    // phase-B persistent c-state: cells c = tid + j*NTHR (j=0..4)
    float cst0 = 0.f, cst1 = 0.f, cst2 = 0.f, cst3 = 0.f, cst4 = 0.f;
    __syncthreads();

    // Pipeline: A(t): L1-gates(t) || L2-gates(t-1) || FC(t-2) || prefetch x(t+1)
    //           B(t): L1-update(t) || L2-update(t-1) || copy x(t+1) into h1 slots
    for (int t = 0; t <= SEQ + 1; ++t) {
        // ================= phase A =================
        if (tid < 300) {
            const bool l1band = (tid < 100);
            const bool act = l1band ? (t < SEQ) : (t >= 1 && t <= SEQ);
            if (act) {
#pragma unroll 2
                for (int b = 0; b < BT; b++) {
                    const ulonglong2* hp = (const ulonglong2*)(hb + b * NPAIR);
                    ull a0 = 0ULL, a1 = 0ULL, c0 = 0ULL, c1 = 0ULL;
#pragma unroll
                    for (int q = 0; q < 14; q++) {
                        ulonglong2 hv = hp[q];          // LDS.128 broadcast, feeds 4 fma2
                        fma2(a0, w2lo[2 * q],     hv.x);
                        fma2(a1, w2lo[2 * q + 1], hv.y);
                        fma2(c0, w2hi[2 * q],     hv.x);
                        fma2(c1, w2hi[2 * q + 1], hv.y);
                    }
                    gd0[b] = add2(a0, a1);              // conflict-free STS.64
                    gd1[b] = add2(c0, c1);
                }
            }
        } else if (tid >= 320 && tid < 336) {
            if (t >= 2) {                               // FC for step t-2
                const int b = tid - 320;
                float a0 = S->bfcs, a1 = 0.f, a2 = 0.f, a3 = 0.f;
#pragma unroll
                for (int q = 0; q < 13; q++) {
                    float4 wv = *(const float4*)&S->wfcs[4 * q];
                    float4 hv = *(const float4*)&S->h2rs[b][4 * q];
                    a0 += wv.x * hv.x; a1 += wv.y * hv.y;
                    a2 += wv.z * hv.z; a3 += wv.w * hv.w;
                }
                out[(t - 2) * BATCH + B0 + b] = (a0 + a1) + (a2 + a3);
            }
        } else if (tid >= 336 && tid < 344) {
            if (t + 1 < SEQ) {                          // prefetch x(t+1) -> xs
                const int i = tid - 336;                // 0..7
#pragma unroll
                for (int j = 0; j < 8; j++) {
                    int idx = i * 8 + j;
                    int b = idx >> 2, d = idx & 3;
                    S->xs[b][d] = x[((t + 1) * BATCH + B0 + b) * IND + d];
                }
            }
        }
        __syncthreads();

        // ================= phase B =================
        // cells: c = tid + j*384 ; c<800 -> L1(t) ; c>=800 -> L2(t-1)
        // j=0,1: all L1. j=2: warp0 L1, warps1-11 L2. j=3: all L2.
        // j=4: warps0-1 L2 tail; warps2-3 copy x(t+1) into h1 slots.
#define CELLJ(JC, CREG)                                                    \
        {                                                                  \
            const int c = tid + (JC) * NTHR;                               \
            const bool l2 = (c >= 800);                                    \
            const int  r  = l2 ? c - 800 : c;                              \
            const int  u  = r >> 4;                                        \
            const int  b  = r & 15;                                        \
            const bool act = l2 ? (t >= 1 && t <= SEQ) : (t < SEQ);        \
            if (act) {                                                     \
                if (!l2) l1_update(S, u, b, CREG);                         \
                else     l2_update(S, u, b, CREG);                         \
            }                                                              \
        }
        CELLJ(0, cst0)
        CELLJ(1, cst1)
        CELLJ(2, cst2)
        CELLJ(3, cst3)
#undef CELLJ
        if (tid < 64) {                                 // j=4 tail: L2 r=736..799
            if (t >= 1 && t <= SEQ) {
                int r = 736 + tid;
                l2_update(S, r >> 4, r & 15, cst4);
            }
        } else if (tid < 128) {
            if (t + 1 < SEQ) {                          // x(t+1) into h1 slots
                int i2 = tid - 64;                      // 0..63
                int b = i2 >> 2, d = i2 & 3;
                S->h1s[b][H + d] = S->xs[b][d];
            }
        }
        __syncthreads();
    }
}

extern "C" void kernel_launch(void* const* d_in, const int* in_sizes, int n_in,
                              void* d_out, int out_size)
{
    const float* x     = (const float*)d_in[0];
    const float* w_ih1 = (const float*)d_in[1];
    const float* w_hh1 = (const float*)d_in[2];
    const float* b_ih1 = (const float*)d_in[3];
    const float* b_hh1 = (const float*)d_in[4];
    const float* w_ih2 = (const float*)d_in[5];
    const float* w_hh2 = (const float*)d_in[6];
    const float* b_ih2 = (const float*)d_in[7];
    const float* b_hh2 = (const float*)d_in[8];
    const float* w_fc  = (const float*)d_in[9];
    const float* b_fc  = (const float*)d_in[10];
    float* out = (float*)d_out;

    cudaFuncSetAttribute(lstm_fused_kernel,
                         cudaFuncAttributeMaxDynamicSharedMemorySize,
                         (int)sizeof(Smem));
    lstm_fused_kernel<<<NCTA, NTHR, sizeof(Smem)>>>(
        x, w_ih1, w_hh1, b_ih1, b_hh1,
        w_ih2, w_hh2, b_ih2, b_hh2, w_fc, b_fc, out);
}

// round 9
// speedup vs baseline: 1.2918x; 1.2918x over previous
#include <cuda_runtime.h>

#define SEQ   512
#define BATCH 2048
#define IND   4
#define H     50
#define BT    16                 // batch tile per CTA
#define NCTA  (BATCH / BT)       // 128
#define NTHR  640                // 20 warps: P group 7 (224 thr), C group 13 (416 thr)
#define HP    56                 // floats per h row: 50 h + 4 x + 2 pad = 28 pairs
#define NPAIR 28
#define GS    17                 // gate-row stride in floats (coprime 32 -> conflict-light)

typedef unsigned long long ull;

// ---- packed dual-fp32 (sm_103a FFMA2 path, PTX-only) ----
__device__ __forceinline__ ull pack2(float lo, float hi) {
    ull r; asm("mov.b64 %0, {%1, %2};" : "=l"(r) : "f"(lo), "f"(hi)); return r;
}
__device__ __forceinline__ void unpack2(ull v, float& lo, float& hi) {
    asm("mov.b64 {%0, %1}, %2;" : "=f"(lo), "=f"(hi) : "l"(v));
}
__device__ __forceinline__ void fma2(ull& d, ull a, ull b) {
    asm("fma.rn.f32x2 %0, %1, %2, %0;" : "+l"(d) : "l"(a), "l"(b));
}

// ---- fast activations (known-good: final rel_err ~1.5e-7) ----
__device__ __forceinline__ float sigf(float x) {
    return __fdividef(1.0f, 1.0f + __expf(-x));
}
__device__ __forceinline__ float tanh_fast(float x) {
    float ax = fabsf(x);
    float e  = __expf(-2.0f * ax);
    float t  = __fdividef(1.0f - e, 1.0f + e);
    return copysignf(t, x);
}

struct __align__(16) Smem {
    float h1s  [BT][HP];     // layer1 h(t-1) + x(t) in slots 50..53, pads zero
    float h1rs2[2][BT][HP];  // relu(h1), DOUBLE-BUFFERED (parity = t&1)
    float h2s  [BT][HP];     // layer2 h
    float h2rs [BT][HP];     // relu(h2) (single: FC reads in C-gate subphase only)
    float g1s [200 * GS];    // L1 gates, scalar, bias folded
    float g2as[200 * GS];    // L2 w_ih2 part, bias folded
    float g2bs[200 * GS];    // L2 w_hh2 part
    float wfcs[52];
    float bfcs;
};

// 28-pair packed dot product: h row via LDS.128 broadcast, w from registers
__device__ __forceinline__ float dot28(const ull* w2, const float* hrow) {
    const ulonglong2* hp = (const ulonglong2*)hrow;
    ull a0 = 0ULL, a1 = 0ULL;
#pragma unroll
    for (int q = 0; q < 14; q++) {
        ulonglong2 hv = hp[q];
        fma2(a0, w2[2 * q],     hv.x);
        fma2(a1, w2[2 * q + 1], hv.y);
    }
    float x0, x1, y0, y1;
    unpack2(a0, x0, x1);
    unpack2(a1, y0, y1);
    return (x0 + x1) + (y0 + y1);
}

__device__ __forceinline__ void l1_cell(Smem* S, int u, int b, int par, float& c) {
    float gi = S->g1s[(      u) * GS + b];
    float gf = S->g1s[(H   + u) * GS + b];
    float gg = S->g1s[(2*H + u) * GS + b];
    float go = S->g1s[(3*H + u) * GS + b];
    float cn = sigf(gf) * c + sigf(gi) * tanh_fast(gg);
    c = cn;
    float hv = sigf(go) * tanh_fast(cn);
    S->h1s[b][u]          = hv;
    S->h1rs2[par][b][u]   = fmaxf(hv, 0.f);
}

__device__ __forceinline__ void l2_cell(Smem* S, int u, int b, float& c) {
    float gi = S->g2as[(      u) * GS + b] + S->g2bs[(      u) * GS + b];
    float gf = S->g2as[(H   + u) * GS + b] + S->g2bs[(H   + u) * GS + b];
    float gg = S->g2as[(2*H + u) * GS + b] + S->g2bs[(2*H + u) * GS + b];
    float go = S->g2as[(3*H + u) * GS + b] + S->g2bs[(3*H + u) * GS + b];
    float cn = sigf(gf) * c + sigf(gi) * tanh_fast(gg);
    c = cn;
    float hv = sigf(go) * tanh_fast(cn);
    S->h2s[b][u]  = hv;
    S->h2rs[b][u] = fmaxf(hv, 0.f);
}

// Named barriers:
//  1: P-internal (count 224)       2: C-internal (count 416)
//  3: FWD  h1rs2 ready   (P arrives 224, C syncs 416; total 640)
//  4: BWD  h1rs2 consumed (C arrives 416, P syncs 224; total 640; P from it>=1)
#define BSYNC(ID, CNT)   asm volatile("bar.sync %0, %1;"   :: "n"(ID), "n"(CNT) : "memory")
#define BARRIVE(ID, CNT) asm volatile("bar.arrive %0, %1;" :: "n"(ID), "n"(CNT) : "memory")

__global__ __launch_bounds__(NTHR, 1)
void lstm_fused_kernel(
    const float* __restrict__ x,
    const float* __restrict__ w_ih1, const float* __restrict__ w_hh1,
    const float* __restrict__ b_ih1, const float* __restrict__ b_hh1,
    const float* __restrict__ w_ih2, const float* __restrict__ w_hh2,
    const float* __restrict__ b_ih2, const float* __restrict__ b_hh2,
    const float* __restrict__ w_fc,  const float* __restrict__ b_fc,
    float* __restrict__ out)
{
    extern __shared__ char smem_raw[];
    Smem* S = (Smem*)smem_raw;

    const int tid = threadIdx.x;
    const int B0  = blockIdx.x * BT;

    // ---- init: zero all h arrays (incl pads) ----
    for (int i = tid; i < 5 * BT * HP; i += NTHR)
        ((float*)S->h1s)[i] = 0.f;
    if (tid < 52)  S->wfcs[tid] = (tid < H) ? w_fc[tid] : 0.f;
    if (tid == 0)  S->bfcs = b_fc[0];

    // ---- per-thread packed weights (uniform 28-pair rows) ----
    // P gates   tid [0,200)    : w_hh1 pairs 0..24, w_ih1 pairs 25..26 -> g1s  (reads h1s)
    // C band1   ct  [0,200)    : w_ih2 pairs 0..24                     -> g2as (reads h1rs2)
    // C band2   ct  [200,400)  : w_hh2 pairs 0..24                     -> g2bs (reads h2s)
    ull w2[NPAIR];
#pragma unroll
    for (int q = 0; q < NPAIR; q++) w2[q] = 0ULL;
    float breg = 0.f;

    if (tid < 200) {
        const int g = tid;
#pragma unroll
        for (int q = 0; q < 25; q++)
            w2[q] = pack2(w_hh1[g * H + 2 * q], w_hh1[g * H + 2 * q + 1]);
        w2[25] = pack2(w_ih1[g * IND + 0], w_ih1[g * IND + 1]);
        w2[26] = pack2(w_ih1[g * IND + 2], w_ih1[g * IND + 3]);
        breg = b_ih1[g] + b_hh1[g];
    } else if (tid >= 224 && tid < 424) {
        const int g = tid - 224;
#pragma unroll
        for (int q = 0; q < 25; q++)
            w2[q] = pack2(w_ih2[g * H + 2 * q], w_ih2[g * H + 2 * q + 1]);
        breg = b_ih2[g] + b_hh2[g];
    } else if (tid >= 424 && tid < 624) {
        const int g = tid - 424;
#pragma unroll
        for (int q = 0; q < 25; q++)
            w2[q] = pack2(w_hh2[g * H + 2 * q], w_hh2[g * H + 2 * q + 1]);
    }

    __syncthreads();
    if (tid < BT * IND) {                          // stage x(0) into h1 slots
        int b = tid >> 2, d = tid & 3;
        S->h1s[b][H + d] = x[(B0 + b) * IND + d];
    }
    __syncthreads();                               // last full-block barrier

    if (tid < 224) {
        // ===================== GROUP P : layer 1 =====================
        float c0 = 0.f, c1 = 0.f, c2 = 0.f, c3 = 0.f;
        for (int it = 0; it < SEQ; ++it) {
            float4 xv = make_float4(0.f, 0.f, 0.f, 0.f);
            if (tid < 200) {                       // L1 gates(it)
                const int g = tid;
#pragma unroll 2
                for (int b = 0; b < BT; b++)
                    S->g1s[g * GS + b] = breg + dot28(w2, S->h1s[b]);
            } else if (tid < 216) {                // prefetch x(it+1) -> regs
                if (it + 1 < SEQ) {
                    const int b = tid - 200;
                    xv = *(const float4*)&x[((it + 1) * BATCH + B0 + b) * IND];
                }
            }
            BSYNC(1, 224);                         // gates done
            if (it >= 1) BSYNC(4, 640);            // wait: C consumed h1rs2[it&1]
            const int par = it & 1;
            if (tid < 200) {                       // L1 cells(it): 4 per thread
                l1_cell(S, (tid +   0) >> 4, tid        & 15, par, c0);
                l1_cell(S, (tid + 200) >> 4, (tid + 200) & 15, par, c1);
                l1_cell(S, (tid + 400) >> 4, (tid + 400) & 15, par, c2);
                l1_cell(S, (tid + 600) >> 4, (tid + 600) & 15, par, c3);
            } else if (tid < 216) {                // x(it+1) into h1 slots
                if (it + 1 < SEQ) {
                    const int b = tid - 200;
                    ((float2*)&S->h1s[b][H])[0] = make_float2(xv.x, xv.y);
                    ((float2*)&S->h1s[b][H])[1] = make_float2(xv.z, xv.w);
                }
            }
            BARRIVE(3, 640);                       // h1rs2[it&1] ready for C
            BSYNC(1, 224);                         // end-of-iteration (h1s stable)
        }
    } else {
        // ===================== GROUP C : layer 2 + FC =====================
        const int ct = tid - 224;
        float c0 = 0.f, c1 = 0.f;
        for (int it = 0; it < SEQ; ++it) {
            BSYNC(3, 640);                         // wait: h1rs2[it&1] ready
            const int par = it & 1;
            if (ct < 200) {                        // band1: w_ih2 . h1r(it)
                const int g = ct;
#pragma unroll 2
                for (int b = 0; b < BT; b++)
                    S->g2as[g * GS + b] = breg + dot28(w2, S->h1rs2[par][b]);
            } else if (ct < 400) {                 // band2: w_hh2 . h2(it-1)
                const int g = ct - 200;
#pragma unroll 2
                for (int b = 0; b < BT; b++)
                    S->g2bs[g * GS + b] = dot28(w2, S->h2s[b]);
            } else {                               // FC for step it-1
                if (it >= 1) {
                    const int b = ct - 400;
                    float a0 = S->bfcs, a1 = 0.f, a2 = 0.f, a3 = 0.f;
#pragma unroll
                    for (int q = 0; q < 13; q++) {
                        float4 wv = *(const float4*)&S->wfcs[4 * q];
                        float4 hv = *(const float4*)&S->h2rs[b][4 * q];
                        a0 += wv.x * hv.x; a1 += wv.y * hv.y;
                        a2 += wv.z * hv.z; a3 += wv.w * hv.w;
                    }
                    out[(it - 1) * BATCH + B0 + b] = (a0 + a1) + (a2 + a3);
                }
            }
            BARRIVE(4, 640);                       // h1rs2[it&1] consumed
            BSYNC(2, 416);                         // gates done (C-internal)
            if (ct < 400) {                        // L2 cells(it): 2 per thread
                l2_cell(S, (ct +   0) >> 4, ct         & 15, c0);
                l2_cell(S, (ct + 400) >> 4, (ct + 400) & 15, c1);
            }
            // next FWD sync doubles as C end-of-iteration rendezvous
        }
        BSYNC(2, 416);                             // cells(511) done
        if (ct >= 400) {                           // tail FC for step 511
            const int b = ct - 400;
            float a0 = S->bfcs, a1 = 0.f, a2 = 0.f, a3 = 0.f;
#pragma unroll
            for (int q = 0; q < 13; q++) {
                float4 wv = *(const float4*)&S->wfcs[4 * q];
                float4 hv = *(const float4*)&S->h2rs[b][4 * q];
                a0 += wv.x * hv.x; a1 += wv.y * hv.y;
                a2 += wv.z * hv.z; a3 += wv.w * hv.w;
            }
            out[511 * BATCH + B0 + b] = (a0 + a1) + (a2 + a3);
        }
    }
}

extern "C" void kernel_launch(void* const* d_in, const int* in_sizes, int n_in,
                              void* d_out, int out_size)
{
    const float* x     = (const float*)d_in[0];
    const float* w_ih1 = (const float*)d_in[1];
    const float* w_hh1 = (const float*)d_in[2];
    const float* b_ih1 = (const float*)d_in[3];
    const float* b_hh1 = (const float*)d_in[4];
    const float* w_ih2 = (const float*)d_in[5];
    const float* w_hh2 = (const float*)d_in[6];
    const float* b_ih2 = (const float*)d_in[7];
    const float* b_hh2 = (const float*)d_in[8];
    const float* w_fc  = (const float*)d_in[9];
    const float* b_fc  = (const float*)d_in[10];
    float* out = (float*)d_out;

    cudaFuncSetAttribute(lstm_fused_kernel,
                         cudaFuncAttributeMaxDynamicSharedMemorySize,
                         (int)sizeof(Smem));
    lstm_fused_kernel<<<NCTA, NTHR, sizeof(Smem)>>>(
        x, w_ih1, w_hh1, b_ih1, b_hh1,
        w_ih2, w_hh2, b_ih2, b_hh2, w_fc, b_fc, out);
}

// round 10
// speedup vs baseline: 1.7899x; 1.3856x over previous
#include <cuda_runtime.h>

#define SEQ   512
#define BATCH 2048
#define IND   4
#define H     50
#define BT    16                 // batch tile per CTA
#define NCTA  (BATCH / BT)       // 128
#define NTHR  640                // 20 warps
#define HP    56                 // floats per h row: 50 h + 4 x + 2 pad = 28 pairs
#define GS2   17                 // pair-row stride in ull (conflict-free)
#define GHALF 1704               // ull offset of hi-half partials (== 8 mod 16)

typedef unsigned long long ull;

// ---- packed dual-fp32 (sm_103a FFMA2 path, PTX-only) ----
__device__ __forceinline__ ull pack2(float lo, float hi) {
    ull r; asm("mov.b64 %0, {%1, %2};" : "=l"(r) : "f"(lo), "f"(hi)); return r;
}
__device__ __forceinline__ void unpack2(ull v, float& lo, float& hi) {
    asm("mov.b64 {%0, %1}, %2;" : "=f"(lo), "=f"(hi) : "l"(v));
}
__device__ __forceinline__ void fma2(ull& d, ull a, ull b) {
    asm("fma.rn.f32x2 %0, %1, %2, %0;" : "+l"(d) : "l"(a), "l"(b));
}
__device__ __forceinline__ ull add2(ull a, ull b) {
    ull r; asm("add.rn.f32x2 %0, %1, %2;" : "=l"(r) : "l"(a), "l"(b)); return r;
}
__device__ __forceinline__ float hsum(ull v) {
    float lo, hi; unpack2(v, lo, hi); return lo + hi;
}

// ---- fast activations (known-good: final rel_err ~1.5e-7) ----
__device__ __forceinline__ float sigf(float x) {
    return __fdividef(1.0f, 1.0f + __expf(-x));
}
__device__ __forceinline__ float tanh_fast(float x) {
    float ax = fabsf(x);
    float e  = __expf(-2.0f * ax);
    float t  = __fdividef(1.0f - e, 1.0f + e);
    return copysignf(t, x);
}

struct __align__(16) Smem {
    float h1s [BT][HP];      // layer1 h (+ x in slots 50..53, pads zero)
    float h1rs[BT][HP];      // relu(h1)  (slots 50..55 stay zero)
    float h2s [BT][HP];      // layer2 h
    float h2rs[BT][HP];      // relu(h2)
    // pair buffers: entry r holds pair (gate row r, gate row r+100);
    // [0..GHALF) = k-lo partials, [GHALF..2*GHALF) = k-hi partials
    ull   gp1 [2 * GHALF];   // L1 gates (bias folded in lo half)
    ull   gp2a[2 * GHALF];   // L2 w_ih2 part (bias folded in lo half)
    ull   gp2b[2 * GHALF];   // L2 w_hh2 part
    float xs[BT][IND];       // staged x(t+1)
    float wfcs[52];
    float bfcs;
};

// L1 cell: gates (i,g) live in pair entry u, (f,o) in entry u+50
__device__ __forceinline__ void l1_cell(Smem* S, int u, int b, float& c) {
    ull ig = add2(S->gp1[        u  * GS2 + b], S->gp1[GHALF +  u       * GS2 + b]);
    ull fo = add2(S->gp1[(u + 50) * GS2 + b], S->gp1[GHALF + (u + 50) * GS2 + b]);
    float gi, gg, gf, go;
    unpack2(ig, gi, gg);
    unpack2(fo, gf, go);
    float cn = sigf(gf) * c + sigf(gi) * tanh_fast(gg);
    c = cn;
    float hv = sigf(go) * tanh_fast(cn);
    S->h1s[b][u]  = hv;
    S->h1rs[b][u] = fmaxf(hv, 0.f);
}

__device__ __forceinline__ void l2_cell(Smem* S, int u, int b, float& c) {
    ull ig = add2(add2(S->gp2a[        u  * GS2 + b], S->gp2a[GHALF +  u       * GS2 + b]),
                  add2(S->gp2b[        u  * GS2 + b], S->gp2b[GHALF +  u       * GS2 + b]));
    ull fo = add2(add2(S->gp2a[(u + 50) * GS2 + b], S->gp2a[GHALF + (u + 50) * GS2 + b]),
                  add2(S->gp2b[(u + 50) * GS2 + b], S->gp2b[GHALF + (u + 50) * GS2 + b]));
    float gi, gg, gf, go;
    unpack2(ig, gi, gg);
    unpack2(fo, gf, go);
    float cn = sigf(gf) * c + sigf(gi) * tanh_fast(gg);
    c = cn;
    float hv = sigf(go) * tanh_fast(cn);
    S->h2s[b][u]  = hv;
    S->h2rs[b][u] = fmaxf(hv, 0.f);
}

__global__ __launch_bounds__(NTHR, 1)
void lstm_fused_kernel(
    const float* __restrict__ x,
    const float* __restrict__ w_ih1, const float* __restrict__ w_hh1,
    const float* __restrict__ b_ih1, const float* __restrict__ b_hh1,
    const float* __restrict__ w_ih2, const float* __restrict__ w_hh2,
    const float* __restrict__ b_ih2, const float* __restrict__ b_hh2,
    const float* __restrict__ w_fc,  const float* __restrict__ b_fc,
    float* __restrict__ out)
{
    extern __shared__ char smem_raw[];
    Smem* S = (Smem*)smem_raw;

    const int tid = threadIdx.x;
    const int B0  = blockIdx.x * BT;

    // ---- init: zero h arrays (incl pads) ----
    for (int i = tid; i < 4 * BT * HP; i += NTHR)
        ((float*)S->h1s)[i] = 0.f;
    if (tid < 52)  S->wfcs[tid] = (tid < H) ? w_fc[tid] : 0.f;
    if (tid == 0)  S->bfcs = b_fc[0];
    __syncthreads();
    if (tid < BT * IND) {                          // x(0) into h1 row slots
        int b = tid >> 2, d = tid & 3;
        S->h1s[b][H + d] = x[(B0 + b) * IND + d];
    }

    // ---- per-thread packed weights: 2 rows x half-k ----
    // tid < 600 : band = tid/200, u = tid%200, half = u&1, r = u>>1 (0..99)
    //   thread covers gate rows r and r+100 of its band, k-pairs [14*half, 14*half+14)
    //   band 0: w_hh1 (+w_ih1 at pairs 25,26)  reads h1s  -> gp1
    //   band 1: w_ih2                          reads h1rs -> gp2a
    //   band 2: w_hh2                          reads h2s  -> gp2b
    ull w2a[14], w2b[14];                          // rows r / r+100, my k-half
#pragma unroll
    for (int q = 0; q < 14; q++) { w2a[q] = 0ULL; w2b[q] = 0ULL; }
    float br0 = 0.f, br1 = 0.f;                    // biases folded into lo half
    const float* hb = &S->h1s[0][0];
    ull* gdst = S->gp1;
    int  hoff = 0;

    if (tid < 600) {
        const int band = tid / 200;
        const int u    = tid - band * 200;
        const int half = u & 1;
        const int r    = u >> 1;                   // 0..99
        hoff = half * 28;                          // float offset of my k-half
        const float* wsrc = (band == 0) ? w_hh1 : (band == 1) ? w_ih2 : w_hh2;
#pragma unroll
        for (int q = 0; q < 14; q++) {
            const int P = 14 * half + q;           // global pair index 0..27
            float alo = 0.f, ahi = 0.f, blo = 0.f, bhi = 0.f;
            if (P < 25) {
                alo = wsrc[(r      ) * H + 2 * P]; ahi = wsrc[(r      ) * H + 2 * P + 1];
                blo = wsrc[(r + 100) * H + 2 * P]; bhi = wsrc[(r + 100) * H + 2 * P + 1];
            } else if (P < 27 && band == 0) {      // x slots (pairs 25,26)
                const int d = (P - 25) * 2;
                alo = w_ih1[(r      ) * IND + d];  ahi = w_ih1[(r      ) * IND + d + 1];
                blo = w_ih1[(r + 100) * IND + d];  bhi = w_ih1[(r + 100) * IND + d + 1];
            }
            w2a[q] = pack2(alo, ahi);
            w2b[q] = pack2(blo, bhi);
        }
        if (half == 0) {
            if (band == 0) { br0 = b_ih1[r] + b_hh1[r]; br1 = b_ih1[r + 100] + b_hh1[r + 100]; }
            if (band == 1) { br0 = b_ih2[r] + b_hh2[r]; br1 = b_ih2[r + 100] + b_hh2[r + 100]; }
        }
        if      (band == 0) { hb = &S->h1s [0][0]; gdst = S->gp1  + half * GHALF + r * GS2; }
        else if (band == 1) { hb = &S->h1rs[0][0]; gdst = S->gp2a + half * GHALF + r * GS2; }
        else                { hb = &S->h2s [0][0]; gdst = S->gp2b + half * GHALF + r * GS2; }
    }

    float cst0 = 0.f, cst1 = 0.f, cst2 = 0.f;      // phase-B c-state
    __syncthreads();

    // Pipeline: A(t): L1-gates(t) || L2-gates(t-1) || FC(t-2) || prefetch x(t+1)
    //           B(t): L1-cells(t) || L2-cells(t-1) || copy x(t+1) into h1 slots
    for (int t = 0; t <= SEQ + 1; ++t) {
        // ================= phase A =================
        if (tid < 600) {
            const bool l1band = (tid < 200);
            const bool act = l1band ? (t < SEQ) : (t >= 1 && t <= SEQ);
            if (act) {
#pragma unroll 2
                for (int b = 0; b < BT; b++) {
                    const ulonglong2* hp = (const ulonglong2*)(hb + b * HP + hoff);
                    ull a0 = 0ULL, a1 = 0ULL, c0 = 0ULL, c1 = 0ULL;
#pragma unroll
                    for (int q = 0; q < 7; q++) {  // 7 LDS.128, 2 lines/phase
                        ulonglong2 hv = hp[q];
                        fma2(a0, w2a[2 * q],     hv.x);
                        fma2(a1, w2a[2 * q + 1], hv.y);
                        fma2(c0, w2b[2 * q],     hv.x);
                        fma2(c1, w2b[2 * q + 1], hv.y);
                    }
                    float p0 = hsum(add2(a0, a1)) + br0;   // row r      (bias lo-half)
                    float p1 = hsum(add2(c0, c1)) + br1;   // row r+100
                    gdst[b] = pack2(p0, p1);               // STS.64, conflict-free
                }
            }
        } else if (tid < 616) {
            if (t >= 2) {                               // FC for step t-2
                const int b = tid - 600;
                float a0 = S->bfcs, a1 = 0.f, a2 = 0.f, a3 = 0.f;
#pragma unroll
                for (int q = 0; q < 13; q++) {
                    float4 wv = *(const float4*)&S->wfcs[4 * q];
                    float4 hv = *(const float4*)&S->h2rs[b][4 * q];
                    a0 += wv.x * hv.x; a1 += wv.y * hv.y;
                    a2 += wv.z * hv.z; a3 += wv.w * hv.w;
                }
                out[(t - 2) * BATCH + B0 + b] = (a0 + a1) + (a2 + a3);
            }
        } else if (tid < 624) {
            if (t + 1 < SEQ) {                          // prefetch x(t+1) -> xs
                const int i = tid - 616;                // 0..7
#pragma unroll
                for (int j = 0; j < 8; j++) {
                    int idx = i * 8 + j;
                    int b = idx >> 2, d = idx & 3;
                    S->xs[b][d] = x[((t + 1) * BATCH + B0 + b) * IND + d];
                }
            }
        }
        __syncthreads();

        // ================= phase B =================
        // cells: c = tid + j*640 ; c<800 -> L1(t) ; c>=800 -> L2(t-1)
        {   // j=0: cells 0..639, all L1
            if (t < SEQ) l1_cell(S, tid >> 4, tid & 15, cst0);
        }
        {   // j=1: tid<160 -> L1 cells 640..799 ; tid>=160 -> L2 r=0..479
            if (tid < 160) {
                if (t < SEQ) { int r = 640 + tid; l1_cell(S, r >> 4, r & 15, cst1); }
            } else {
                if (t >= 1 && t <= SEQ) { int r = tid - 160; l2_cell(S, r >> 4, r & 15, cst1); }
            }
        }
        {   // j=2: tid<320 -> L2 r=480..799 ; tid in [320,384) -> x copy
            if (tid < 320) {
                if (t >= 1 && t <= SEQ) { int r = 480 + tid; l2_cell(S, r >> 4, r & 15, cst2); }
            } else if (tid < 384) {
                if (t + 1 < SEQ) {
                    int i2 = tid - 320;                 // 0..63
                    int b = i2 >> 2, d = i2 & 3;
                    S->h1s[b][H + d] = S->xs[b][d];     // x(t+1) into h1 slots
                }
            }
        }
        __syncthreads();
    }
}

extern "C" void kernel_launch(void* const* d_in, const int* in_sizes, int n_in,
                              void* d_out, int out_size)
{
    const float* x     = (const float*)d_in[0];
    const float* w_ih1 = (const float*)d_in[1];
    const float* w_hh1 = (const float*)d_in[2];
    const float* b_ih1 = (const float*)d_in[3];
    const float* b_hh1 = (const float*)d_in[4];
    const float* w_ih2 = (const float*)d_in[5];
    const float* w_hh2 = (const float*)d_in[6];
    const float* b_ih2 = (const float*)d_in[7];
    const float* b_hh2 = (const float*)d_in[8];
    const float* w_fc  = (const float*)d_in[9];
    const float* b_fc  = (const float*)d_in[10];
    float* out = (float*)d_out;

    cudaFuncSetAttribute(lstm_fused_kernel,
                         cudaFuncAttributeMaxDynamicSharedMemorySize,
                         (int)sizeof(Smem));
    lstm_fused_kernel<<<NCTA, NTHR, sizeof(Smem)>>>(
        x, w_ih1, w_hh1, b_ih1, b_hh1,
        w_ih2, w_hh2, b_ih2, b_hh2, w_fc, b_fc, out);
}

// round 12
// speedup vs baseline: 1.8941x; 1.0582x over previous
#include <cuda_runtime.h>

#define SEQ   512
#define BATCH 2048
#define IND   4
#define H     50
#define NTHR  640                // 20 warps
#define HP    56                 // floats per h row: 50 h + 4 x + 2 pad = 28 pairs
#define NBLK  147                // 146 CTAs x BT=14  +  1 CTA x BT=4  (one 148-SM wave)
#define MAINBT 14

typedef unsigned long long ull;

// ---- packed dual-fp32 (sm_103a FFMA2 path, PTX-only) ----
__device__ __forceinline__ ull pack2(float lo, float hi) {
    ull r; asm("mov.b64 %0, {%1, %2};" : "=l"(r) : "f"(lo), "f"(hi)); return r;
}
__device__ __forceinline__ void unpack2(ull v, float& lo, float& hi) {
    asm("mov.b64 {%0, %1}, %2;" : "=f"(lo), "=f"(hi) : "l"(v));
}
__device__ __forceinline__ void fma2(ull& d, ull a, ull b) {
    asm("fma.rn.f32x2 %0, %1, %2, %0;" : "+l"(d) : "l"(a), "l"(b));
}
__device__ __forceinline__ ull add2(ull a, ull b) {
    ull r; asm("add.rn.f32x2 %0, %1, %2;" : "=l"(r) : "l"(a), "l"(b)); return r;
}
__device__ __forceinline__ float hsum(ull v) {
    float lo, hi; unpack2(v, lo, hi); return lo + hi;
}

// ---- fast activations (known-good: final rel_err ~1.5e-7) ----
__device__ __forceinline__ float sigf(float x) {
    return __fdividef(1.0f, 1.0f + __expf(-x));
}
__device__ __forceinline__ float tanh_fast(float x) {
    float ax = fabsf(x);
    float e  = __expf(-2.0f * ax);
    float t  = __fdividef(1.0f - e, 1.0f + e);
    return copysignf(t, x);
}

// GHALF: offset of the hi-half partial buffer; padded so GHALF % 16 == 8
// (keeps the two k-half STS.64 streams on disjoint bank-pair phases).
constexpr int ghalf_of(int gs2) {
    return 100 * gs2 + ((8 - 100 * gs2) & 15);
}

template<int BT>
struct __align__(16) Smem {
    static constexpr int GS2 = BT + 1;            // pair-row stride (conflict-free pad)
    static constexpr int GH  = ghalf_of(GS2);
    float h1s [BT][HP];      // layer1 h (+ x in slots 50..53, pads zero)
    float h1rs[BT][HP];      // relu(h1)
    float h2s [BT][HP];      // layer2 h
    float h2rs[BT][HP];      // relu(h2)
    ull   gp1 [2 * GH];      // L1 gates: entry r = pair(row r, row r+100); lo/hi k-half
    ull   gp2a[2 * GH];      // L2 w_ih2 part
    ull   gp2b[2 * GH];      // L2 w_hh2 part
    float xs[BT][IND];       // staged x(t+1)
    float wfcs[52];
    float bfcs;
};

// cells: unit u in [0,50). Pair entry u holds gates (i_u, g_u); entry u+50 holds (f_u, o_u).
template<int BT>
__device__ __forceinline__ void l1_cell(Smem<BT>* S, int u, int b, float& c) {
    constexpr int GS2 = Smem<BT>::GS2, GH = Smem<BT>::GH;
    ull ig = add2(S->gp1[      u  * GS2 + b], S->gp1[GH +       u  * GS2 + b]);
    ull fo = add2(S->gp1[(u + 50) * GS2 + b], S->gp1[GH + (u + 50) * GS2 + b]);
    float gi, gg, gf, go;
    unpack2(ig, gi, gg);
    unpack2(fo, gf, go);
    float cn = sigf(gf) * c + sigf(gi) * tanh_fast(gg);
    c = cn;
    float hv = sigf(go) * tanh_fast(cn);
    S->h1s[b][u]  = hv;
    S->h1rs[b][u] = fmaxf(hv, 0.f);
}

template<int BT>
__device__ __forceinline__ void l2_cell(Smem<BT>* S, int u, int b, float& c) {
    constexpr int GS2 = Smem<BT>::GS2, GH = Smem<BT>::GH;
    ull ig = add2(add2(S->gp2a[      u  * GS2 + b], S->gp2a[GH +       u  * GS2 + b]),
                  add2(S->gp2b[      u  * GS2 + b], S->gp2b[GH +       u  * GS2 + b]));
    ull fo = add2(add2(S->gp2a[(u + 50) * GS2 + b], S->gp2a[GH + (u + 50) * GS2 + b]),
                  add2(S->gp2b[(u + 50) * GS2 + b], S->gp2b[GH + (u + 50) * GS2 + b]));
    float gi, gg, gf, go;
    unpack2(ig, gi, gg);
    unpack2(fo, gf, go);
    float cn = sigf(gf) * c + sigf(gi) * tanh_fast(gg);
    c = cn;
    float hv = sigf(go) * tanh_fast(cn);
    S->h2s[b][u]  = hv;
    S->h2rs[b][u] = fmaxf(hv, 0.f);
}

template<int BT>
__device__ __forceinline__ void run_lstm(
    char* smem_raw, int B0,
    const float* __restrict__ x,
    const float* __restrict__ w_ih1, const float* __restrict__ w_hh1,
    const float* __restrict__ b_ih1, const float* __restrict__ b_hh1,
    const float* __restrict__ w_ih2, const float* __restrict__ w_hh2,
    const float* __restrict__ b_ih2, const float* __restrict__ b_hh2,
    const float* __restrict__ w_fc,  const float* __restrict__ b_fc,
    float* __restrict__ out)
{
    Smem<BT>* S = (Smem<BT>*)smem_raw;
    constexpr int GS2 = Smem<BT>::GS2, GH = Smem<BT>::GH;
    constexpr int N1  = H * BT;                    // cells per layer (R11 bug: was 100*BT)

    const int tid = threadIdx.x;

    // ---- init: zero h arrays (incl pads) ----
    for (int i = tid; i < 4 * BT * HP; i += NTHR)
        ((float*)S->h1s)[i] = 0.f;
    if (tid < 52)  S->wfcs[tid] = (tid < H) ? w_fc[tid] : 0.f;
    if (tid == 0)  S->bfcs = b_fc[0];
    __syncthreads();
    if (tid < BT * IND) {                          // x(0) into h1 row slots
        int b = tid >> 2, d = tid & 3;
        S->h1s[b][H + d] = x[(B0 + b) * IND + d];
    }

    // ---- per-thread packed weights: 2 rows x half-k (proven R10 scheme) ----
    ull w2a[14], w2b[14];
#pragma unroll
    for (int q = 0; q < 14; q++) { w2a[q] = 0ULL; w2b[q] = 0ULL; }
    float br0 = 0.f, br1 = 0.f;
    const float* hb = &S->h1s[0][0];
    ull* gdst = S->gp1;
    int  hoff = 0;

    if (tid < 600) {
        const int band = tid / 200;
        const int u    = tid - band * 200;
        const int half = u & 1;
        const int r    = u >> 1;                   // pair index 0..99
        hoff = half * 28;
        const float* wsrc = (band == 0) ? w_hh1 : (band == 1) ? w_ih2 : w_hh2;
#pragma unroll
        for (int q = 0; q < 14; q++) {
            const int P = 14 * half + q;
            float alo = 0.f, ahi = 0.f, blo = 0.f, bhi = 0.f;
            if (P < 25) {
                alo = wsrc[(r      ) * H + 2 * P]; ahi = wsrc[(r      ) * H + 2 * P + 1];
                blo = wsrc[(r + 100) * H + 2 * P]; bhi = wsrc[(r + 100) * H + 2 * P + 1];
            } else if (P < 27 && band == 0) {
                const int d = (P - 25) * 2;
                alo = w_ih1[(r      ) * IND + d];  ahi = w_ih1[(r      ) * IND + d + 1];
                blo = w_ih1[(r + 100) * IND + d];  bhi = w_ih1[(r + 100) * IND + d + 1];
            }
            w2a[q] = pack2(alo, ahi);
            w2b[q] = pack2(blo, bhi);
        }
        if (half == 0) {
            if (band == 0) { br0 = b_ih1[r] + b_hh1[r]; br1 = b_ih1[r + 100] + b_hh1[r + 100]; }
            if (band == 1) { br0 = b_ih2[r] + b_hh2[r]; br1 = b_ih2[r + 100] + b_hh2[r + 100]; }
        }
        if      (band == 0) { hb = &S->h1s [0][0]; gdst = S->gp1  + half * GH + r * GS2; }
        else if (band == 1) { hb = &S->h1rs[0][0]; gdst = S->gp2a + half * GH + r * GS2; }
        else                { hb = &S->h2s [0][0]; gdst = S->gp2b + half * GH + r * GS2; }
    }

    float cst[3];
#pragma unroll
    for (int j = 0; j < 3; j++) cst[j] = 0.f;
    __syncthreads();

    // Pipeline: A(t): L1-gates(t) || L2-gates(t-1) || FC(t-2) || prefetch x(t+1)
    //           B(t): L1-cells(t) || L2-cells(t-1) || copy x(t+1) into h1 slots
    for (int t = 0; t <= SEQ + 1; ++t) {
        // ================= phase A =================
        if (tid < 600) {
            const bool l1band = (tid < 200);
            const bool act = l1band ? (t < SEQ) : (t >= 1 && t <= SEQ);
            if (act) {
#pragma unroll 2
                for (int b = 0; b < BT; b++) {
                    const ulonglong2* hp = (const ulonglong2*)(hb + b * HP + hoff);
                    ull a0 = 0ULL, a1 = 0ULL, c0 = 0ULL, c1 = 0ULL;
#pragma unroll
                    for (int q = 0; q < 7; q++) {  // 7 LDS.128, 2 lines/phase
                        ulonglong2 hv = hp[q];
                        fma2(a0, w2a[2 * q],     hv.x);
                        fma2(a1, w2a[2 * q + 1], hv.y);
                        fma2(c0, w2b[2 * q],     hv.x);
                        fma2(c1, w2b[2 * q + 1], hv.y);
                    }
                    float p0 = hsum(add2(a0, a1)) + br0;   // row r
                    float p1 = hsum(add2(c0, c1)) + br1;   // row r+100
                    gdst[b] = pack2(p0, p1);               // STS.64, conflict-free
                }
            }
        } else if (tid >= 600 && tid < 600 + BT) {
            if (t >= 2) {                               // FC for step t-2
                const int b = tid - 600;
                float a0 = S->bfcs, a1 = 0.f, a2 = 0.f, a3 = 0.f;
#pragma unroll
                for (int q = 0; q < 13; q++) {
                    float4 wv = *(const float4*)&S->wfcs[4 * q];
                    float4 hv = *(const float4*)&S->h2rs[b][4 * q];
                    a0 += wv.x * hv.x; a1 += wv.y * hv.y;
                    a2 += wv.z * hv.z; a3 += wv.w * hv.w;
                }
                out[(t - 2) * BATCH + B0 + b] = (a0 + a1) + (a2 + a3);
            }
        } else if (tid >= 624 && tid < 632) {
            if (t + 1 < SEQ) {                          // prefetch x(t+1) -> xs
                const int i = tid - 624;                // 0..7
#pragma unroll
                for (int j = 0; j < 7; j++) {
                    int idx = i * 7 + j;
                    if (idx < IND * BT) {
                        int b = idx >> 2, d = idx & 3;
                        S->xs[b][d] = x[((t + 1) * BATCH + B0 + b) * IND + d];
                    }
                }
            }
        }
        __syncthreads();

        // ================= phase B =================
        // cells c = tid + j*NTHR : c<N1 -> L1(t), unit u=c/BT ; N1<=c<2*N1 -> L2(t-1)
#pragma unroll
        for (int j = 0; j < 3; j++) {
            const int c = tid + j * NTHR;
            if (c < N1) {
                if (t < SEQ) l1_cell<BT>(S, c / BT, c % BT, cst[j]);
            } else if (c < 2 * N1) {
                if (t >= 1 && t <= SEQ) {
                    const int r = c - N1;
                    l2_cell<BT>(S, r / BT, r % BT, cst[j]);
                }
            }
        }
        if (tid >= 320 && tid < 320 + IND * BT) {       // x(t+1) into h1 slots
            if (t + 1 < SEQ) {
                int i2 = tid - 320;
                int b = i2 >> 2, d = i2 & 3;
                S->h1s[b][H + d] = S->xs[b][d];
            }
        }
        __syncthreads();
    }
}

__global__ __launch_bounds__(NTHR, 1)
void lstm_fused_kernel(
    const float* __restrict__ x,
    const float* __restrict__ w_ih1, const float* __restrict__ w_hh1,
    const float* __restrict__ b_ih1, const float* __restrict__ b_hh1,
    const float* __restrict__ w_ih2, const float* __restrict__ w_hh2,
    const float* __restrict__ b_ih2, const float* __restrict__ b_hh2,
    const float* __restrict__ w_fc,  const float* __restrict__ b_fc,
    float* __restrict__ out)
{
    extern __shared__ char smem_raw[];
    if (blockIdx.x < NBLK - 1) {
        run_lstm<MAINBT>(smem_raw, blockIdx.x * MAINBT,
                         x, w_ih1, w_hh1, b_ih1, b_hh1,
                         w_ih2, w_hh2, b_ih2, b_hh2, w_fc, b_fc, out);
    } else {
        run_lstm<4>(smem_raw, (NBLK - 1) * MAINBT,   // 146*14 = 2044, last 4 batches
                    x, w_ih1, w_hh1, b_ih1, b_hh1,
                    w_ih2, w_hh2, b_ih2, b_hh2, w_fc, b_fc, out);
    }
}

extern "C" void kernel_launch(void* const* d_in, const int* in_sizes, int n_in,
                              void* d_out, int out_size)
{
    const float* x     = (const float*)d_in[0];
    const float* w_ih1 = (const float*)d_in[1];
    const float* w_hh1 = (const float*)d_in[2];
    const float* b_ih1 = (const float*)d_in[3];
    const float* b_hh1 = (const float*)d_in[4];
    const float* w_ih2 = (const float*)d_in[5];
    const float* w_hh2 = (const float*)d_in[6];
    const float* b_ih2 = (const float*)d_in[7];
    const float* b_hh2 = (const float*)d_in[8];
    const float* w_fc  = (const float*)d_in[9];
    const float* b_fc  = (const float*)d_in[10];
    float* out = (float*)d_out;

    const int smem = (int)sizeof(Smem<MAINBT>);
    cudaFuncSetAttribute(lstm_fused_kernel,
                         cudaFuncAttributeMaxDynamicSharedMemorySize, smem);
    lstm_fused_kernel<<<NBLK, NTHR, smem>>>(
        x, w_ih1, w_hh1, b_ih1, b_hh1,
        w_ih2, w_hh2, b_ih2, b_hh2, w_fc, b_fc, out);
}